// round 3
// baseline (speedup 1.0000x reference)
#include <cuda_runtime.h>

#define SEQ   256
#define LAB   128
#define BATCH 8192
#define NF    8
#define HD    64
#define G3    192
#define NW    8            // warps per block
#define NTHR  (NW * 32)    // 256
#define RPW   4            // rows per warp
#define TB    (NW * RPW)   // 32 rows per block
#define NBLK  (BATCH / TB) // 256 blocks
#define HSTR  68           // h row stride (floats): 16B-aligned, conflict-free

// ---- SMEM layout (float offsets), single weight set (reloaded at phase swap) ----
#define OFF_WIH   0                        // [8][192]   k-major
#define OFF_WHH   (OFF_WIH + NF*G3)        // [64][192]  k-major
#define OFF_B     (OFF_WHH + HD*G3)        // [4][64]    r, z, n_i, n_h
#define OFF_WOUT  (OFF_B + 4*HD)           // [64][4][2] pair (Wout[o4][k], Wout[o4+4][k])
#define OFF_BOUT  (OFF_WOUT + HD*8)        // [4][2]
#define OFF_H     (OFF_BOUT + 8)           // [32][68]
#define OFF_XS    (OFF_H + TB*HSTR)        // [8 warps][2][32]
#define SMEM_FLOATS (OFF_XS + NW*2*32)
#define SMEM_BYTES  (SMEM_FLOATS * sizeof(float))

typedef unsigned long long u64;

__device__ __forceinline__ u64 f2fma(u64 a, u64 b, u64 c) {
    u64 d;
    asm("fma.rn.f32x2 %0, %1, %2, %3;" : "=l"(d) : "l"(a), "l"(b), "l"(c));
    return d;
}
__device__ __forceinline__ u64 splat2(float v) {
    u64 d;
    asm("mov.b64 %0, {%1, %1};" : "=l"(d) : "f"(v));
    return d;
}
__device__ __forceinline__ void unpk(u64 v, float& a, float& b) {
    asm("mov.b64 {%0, %1}, %2;" : "=f"(a), "=f"(b) : "l"(v));
}
__device__ __forceinline__ float tanha(float x) {
    float y;
    asm("tanh.approx.f32 %0, %1;" : "=f"(y) : "f"(x));
    return y;
}
__device__ __forceinline__ float sigt(float x) {          // sigmoid via HW tanh
    return fmaf(0.5f, tanha(0.5f * x), 0.5f);
}

// One GRU step for this warp's 4 rows x 64 units. Warp-private (no block sync).
__device__ __forceinline__ void gru_step(
    const float* __restrict__ wih,   // [8][192]  k-major
    const float* __restrict__ whh,   // [64][192] k-major
    u64 br, u64 bz, u64 bni, u64 bnh,
    const float* __restrict__ xs,    // [4 rows][8 feats] staged x_t
    float* __restrict__ hwp,         // [4 rows][HSTR]
    int lane2)
{
    u64 ar[RPW], az[RPW], an[RPW], ah[RPW];
    #pragma unroll
    for (int r = 0; r < RPW; r++) { ar[r] = br; az[r] = bz; an[r] = bni; ah[r] = bnh; }

    // ---- input GEMM: k = 0..7 ----
    #pragma unroll
    for (int k = 0; k < NF; k += 2) {
        float2 xv[RPW];
        #pragma unroll
        for (int r = 0; r < RPW; r++) xv[r] = *(const float2*)&xs[r * NF + k];
        #pragma unroll
        for (int kk = 0; kk < 2; kk++) {
            const float* w = wih + (k + kk) * G3 + lane2;
            u64 wr = *(const u64*)(w);
            u64 wz = *(const u64*)(w + 64);
            u64 wn = *(const u64*)(w + 128);
            #pragma unroll
            for (int r = 0; r < RPW; r++) {
                u64 hs = splat2(kk ? xv[r].y : xv[r].x);
                ar[r] = f2fma(hs, wr, ar[r]);
                az[r] = f2fma(hs, wz, az[r]);
                an[r] = f2fma(hs, wn, an[r]);
            }
        }
    }

    // ---- recurrent GEMM: k = 0..63 ----
    #pragma unroll 4
    for (int k = 0; k < HD; k += 2) {
        float2 hv[RPW];
        #pragma unroll
        for (int r = 0; r < RPW; r++) hv[r] = *(const float2*)&hwp[r * HSTR + k];
        #pragma unroll
        for (int kk = 0; kk < 2; kk++) {
            const float* w = whh + (k + kk) * G3 + lane2;
            u64 wr = *(const u64*)(w);
            u64 wz = *(const u64*)(w + 64);
            u64 wn = *(const u64*)(w + 128);
            #pragma unroll
            for (int r = 0; r < RPW; r++) {
                u64 hs = splat2(kk ? hv[r].y : hv[r].x);
                ar[r] = f2fma(hs, wr, ar[r]);
                az[r] = f2fma(hs, wz, az[r]);
                ah[r] = f2fma(hs, wn, ah[r]);
            }
        }
    }
    __syncwarp();

    // ---- gates + h update (lane owns units lane2, lane2+1) ----
    #pragma unroll
    for (int r = 0; r < RPW; r++) {
        float r0, r1, z0, z1, i0, i1, g0, g1;
        unpk(ar[r], r0, r1); unpk(az[r], z0, z1);
        unpk(an[r], i0, i1); unpk(ah[r], g0, g1);
        float R0 = sigt(r0), R1 = sigt(r1);
        float Z0 = sigt(z0), Z1 = sigt(z1);
        float N0 = tanha(fmaf(R0, g0, i0));
        float N1 = tanha(fmaf(R1, g1, i1));
        float2 ho = *(const float2*)&hwp[r * HSTR + lane2];
        float2 hn;
        hn.x = fmaf(Z0, ho.x - N0, N0);
        hn.y = fmaf(Z1, ho.y - N1, N1);
        *(float2*)&hwp[r * HSTR + lane2] = hn;
    }
    __syncwarp();
}

__device__ __forceinline__ void load_weights(
    float* wih, float* whh, float* bias,
    const float* __restrict__ Wih, const float* __restrict__ Whh,
    const float* __restrict__ bih, const float* __restrict__ bhh, int tid)
{
    for (int i = tid; i < NF * G3; i += NTHR) {
        int k = i / G3, g = i % G3;
        wih[i] = Wih[g * NF + k];
    }
    for (int i = tid; i < HD * G3; i += NTHR) {
        int k = i / G3, g = i % G3;
        whh[i] = Whh[g * HD + k];
    }
    if (tid < HD) {
        bias[tid]       = bih[tid]      + bhh[tid];
        bias[64 + tid]  = bih[64 + tid] + bhh[64 + tid];
        bias[128 + tid] = bih[128 + tid];
        bias[192 + tid] = bhh[128 + tid];
    }
}

__global__ __launch_bounds__(NTHR, 2)
void seq2seq_gru_kernel(const float* __restrict__ x,
                        const float* __restrict__ xy,
                        const float* __restrict__ eWih, const float* __restrict__ eWhh,
                        const float* __restrict__ ebih, const float* __restrict__ ebhh,
                        const float* __restrict__ dWih, const float* __restrict__ dWhh,
                        const float* __restrict__ dbih, const float* __restrict__ dbhh,
                        const float* __restrict__ Wout, const float* __restrict__ bout,
                        float* __restrict__ out)
{
    extern __shared__ float smem[];
    float* wih   = smem + OFF_WIH;
    float* whh   = smem + OFF_WHH;
    float* bias  = smem + OFF_B;
    float* woutp = smem + OFF_WOUT;
    float* boutp = smem + OFF_BOUT;
    float* hall  = smem + OFF_H;
    float* xsall = smem + OFF_XS;

    const int tid   = threadIdx.x;
    const int lane  = tid & 31;
    const int warp  = tid >> 5;
    const int lane2 = lane * 2;
    const int rowb  = blockIdx.x * TB + warp * RPW;

    float* hwp = hall + warp * RPW * HSTR;
    float* xsw = xsall + warp * 64;                   // two 32-float buffers

    // ---- encoder weights + out-proj constants + zero h ----
    load_weights(wih, whh, bias, eWih, eWhh, ebih, ebhh, tid);
    for (int i = tid; i < HD * 8; i += NTHR) {        // woutp[k][o4][s] = Wout[o4+4s][k]
        int k = i / 8, rem = i % 8, o4 = rem >> 1, s = rem & 1;
        woutp[i] = Wout[(o4 + 4 * s) * HD + k];
    }
    if (tid < 8) { int o4 = tid >> 1, s = tid & 1; boutp[tid] = bout[o4 + 4 * s]; }
    for (int i = tid; i < TB * HSTR; i += NTHR) hall[i] = 0.0f;
    __syncthreads();

    u64 br  = *(const u64*)&bias[lane2];
    u64 bz  = *(const u64*)&bias[64 + lane2];
    u64 bni = *(const u64*)&bias[128 + lane2];
    u64 bnh = *(const u64*)&bias[192 + lane2];

    // =========================== ENCODER ===========================
    {
        // 4 rows x 8 feats = 32 contiguous floats per warp; lane loads one
        float rx = x[((size_t)0 * BATCH + rowb) * NF + lane];
        xsw[lane] = rx;                               // buffer 0
        __syncwarp();
        for (int t = 0; t < SEQ; t++) {
            if (t + 1 < SEQ)
                rx = x[((size_t)(t + 1) * BATCH + rowb) * NF + lane];
            gru_step(wih, whh, br, bz, bni, bnh,
                     xsw + (t & 1) * 32, hwp, lane2);
            if (t + 1 < SEQ)
                xsw[((t + 1) & 1) * 32 + lane] = rx;
            __syncwarp();
        }
    }

    // ---- phase swap: decoder weights ----
    __syncthreads();
    load_weights(wih, whh, bias, dWih, dWhh, dbih, dbhh, tid);
    __syncthreads();

    br  = *(const u64*)&bias[lane2];
    bz  = *(const u64*)&bias[64 + lane2];
    bni = *(const u64*)&bias[128 + lane2];
    bnh = *(const u64*)&bias[192 + lane2];

    // =========================== DECODER ===========================
    const int orow = lane >> 2;        // lanes 0..15: row 0..3
    const int oo4  = lane & 3;
    u64 bop = *(const u64*)&boutp[oo4 * 2];

    {
        float rx = xy[(size_t)rowb * NF + lane];
        xsw[lane] = rx;                               // buffer 0
        __syncwarp();

        for (int t = 0; t < LAB; t++) {
            gru_step(wih, whh, br, bz, bni, bnh,
                     xsw + (t & 1) * 32, hwp, lane2);

            if (lane < 16) {
                // out = h_new @ Wout^T + bout  (outputs o4, o4+4 per lane)
                u64 acc = bop;
                const float* hrow = hwp + orow * HSTR;
                #pragma unroll
                for (int k = 0; k < HD; k += 4) {
                    float4 hh = *(const float4*)&hrow[k];
                    u64 w0 = *(const u64*)&woutp[(k + 0) * 8 + oo4 * 2];
                    u64 w1 = *(const u64*)&woutp[(k + 1) * 8 + oo4 * 2];
                    u64 w2 = *(const u64*)&woutp[(k + 2) * 8 + oo4 * 2];
                    u64 w3 = *(const u64*)&woutp[(k + 3) * 8 + oo4 * 2];
                    acc = f2fma(splat2(hh.x), w0, acc);
                    acc = f2fma(splat2(hh.y), w1, acc);
                    acc = f2fma(splat2(hh.z), w2, acc);
                    acc = f2fma(splat2(hh.w), w3, acc);
                }
                float oa, ob; unpk(acc, oa, ob);

                float* og = out + ((size_t)t * BATCH + rowb + orow) * NF;
                og[oo4]     = oa;
                og[oo4 + 4] = ob;

                if (t + 1 < LAB) {
                    float* nb = xsw + ((t + 1) & 1) * 32 + orow * NF;
                    nb[oo4]     = oa;
                    nb[oo4 + 4] = ob;
                }
            }
            __syncwarp();
        }
    }
}

extern "C" void kernel_launch(void* const* d_in, const int* in_sizes, int n_in,
                              void* d_out, int out_size) {
    (void)in_sizes; (void)n_in; (void)out_size;
    const float* x     = (const float*)d_in[0];
    const float* xy    = (const float*)d_in[1];
    const float* eWih  = (const float*)d_in[2];
    const float* eWhh  = (const float*)d_in[3];
    const float* ebih  = (const float*)d_in[4];
    const float* ebhh  = (const float*)d_in[5];
    const float* dWih  = (const float*)d_in[6];
    const float* dWhh  = (const float*)d_in[7];
    const float* dbih  = (const float*)d_in[8];
    const float* dbhh  = (const float*)d_in[9];
    const float* Wout  = (const float*)d_in[10];
    const float* bout  = (const float*)d_in[11];
    float* out = (float*)d_out;

    cudaFuncSetAttribute(seq2seq_gru_kernel,
                         cudaFuncAttributeMaxDynamicSharedMemorySize, SMEM_BYTES);
    seq2seq_gru_kernel<<<NBLK, NTHR, SMEM_BYTES>>>(
        x, xy, eWih, eWhh, ebih, ebhh, dWih, dWhh, dbih, dbhh, Wout, bout, out);
}